// round 13
// baseline (speedup 1.0000x reference)
#include <cuda_runtime.h>
#include <cstdint>
#include <math.h>

// Problem constants (fixed by the reference)
#define T_STEPS 250
#define NCH     3
#define DFEAT   40
#define IN_DIM  120     // NCH*DFEAT
#define NHID    200
#define NHPAD   224     // spike row padded (zero tail) for 7x32 readout chunks
#define NBR     8
#define PER     15      // IN_DIM / NBR
#define ODIM    35
#define NB      4       // batch elements per CTA
#define NPARTS  7       // readout partial-sum parts (7*32 = 224)
#define THREADS 256
#define WROW    128     // padded weight row: [j4 0..3][k 0..7][e 0..3]

// k-interleaved chunk layout for both x and weights:
//   slot(row, k, j) = row*128 + (j>>2)*32 + k*4 + (j&3),  j in 0..15 (j=15 pad)
// A warp phase (8 lanes, k=0..7, same j4) reads 8 consecutive 16B chunks =
// 128 B covering all 32 banks exactly once -> conflict-free LDS.128/LDG.128.

// Repacked masked W1 lives in a device-global scratch (no SMEM size limit,
// L1-resident after step 1). 200 rows x 128 floats = 100 KB.
__device__ float g_wsm[NHID * WROW];

__global__ void repack_kernel(const float* __restrict__ W1) {
    const int idx = blockIdx.x * THREADS + threadIdx.x;   // < 25600
    const int n  = idx >> 7;
    const int r  = idx & 127;
    const int j4 = r >> 5;
    const int k  = (r >> 2) & 7;
    const int e  = r & 3;
    const int j  = j4 * 4 + e;
    g_wsm[idx] = (j < PER)
        ? W1[(size_t)(n * NBR + k) * IN_DIM + k * PER + j] : 0.0f;
}

// ---------------- packed f32x2 helpers (sm_100a) ----------------
__device__ __forceinline__ unsigned long long ffma2(unsigned long long a,
                                                    unsigned long long b,
                                                    unsigned long long c) {
    unsigned long long d;
    asm("fma.rn.f32x2 %0, %1, %2, %3;" : "=l"(d) : "l"(a), "l"(b), "l"(c));
    return d;
}
__device__ __forceinline__ unsigned long long add2(unsigned long long a,
                                                   unsigned long long b) {
    unsigned long long d;
    asm("add.rn.f32x2 %0, %1, %2;" : "=l"(d) : "l"(a), "l"(b));
    return d;
}
__device__ __forceinline__ float2 unpack2(unsigned long long u) {
    float lo, hi;
    asm("mov.b64 {%0, %1}, %2;" : "=f"(lo), "=f"(hi) : "l"(u));
    return make_float2(lo, hi);
}
__device__ __forceinline__ float sigmoid_acc(float v) {
    return 1.0f / (1.0f + expf(-v));
}
// Volatile LDG.128: prevents hoisting the per-step weight stream into
// persistent registers (which is what pegged earlier kernels at 255 regs).
__device__ __forceinline__ float4 ldg128v(const float* p) {
    float4 v;
    asm volatile("ld.global.nc.v4.f32 {%0,%1,%2,%3}, [%4];"
                 : "=f"(v.x), "=f"(v.y), "=f"(v.z), "=f"(v.w) : "l"(p));
    return v;
}

// One CTA = NB=4 batch elements (grid 128 = one wave). Thread (k = tid&7,
// l = tid>>3) holds x[4 batches][branch k] in registers (16 float4, loaded
// once per step) and STREAMS weight rows for neurons n = l+32m from g_wsm.
// Each 16B weight load feeds 16 MACs (4 batches x 4 weights) vs 1 MAC/4B in
// the weights-in-registers design -> ~3x less L1 traffic per step.
__global__ void __launch_bounds__(THREADS, 1) snn_kernel(
    const float* __restrict__ x,       // [B, 3, 250, 40]
    const float* __restrict__ b1,      // [200]
    const float* __restrict__ tau_m1,  // [200]
    const float* __restrict__ tau_n1,  // [200, 8]
    const float* __restrict__ W2,      // [35, 200]
    const float* __restrict__ b2,      // [35]
    const float* __restrict__ tau_m2,  // [35]
    float* __restrict__ out,           // [B, 35]
    int B)
{
    __shared__ __align__(16) float xbuf[NB * 128];        // k-interleaved xt
    __shared__ __align__(16) float spk_s[NB][NHPAD];      // spikes, zero tail
    __shared__ float psum[NPARTS][NB][ODIM + 1];          // readout partials
    __shared__ float accbuf[NB][ODIM];                    // log-softmax staging

    const int tid = threadIdx.x;
    const int b0  = blockIdx.x * NB;

    // ---- one-time zeroing: spike tails + xbuf pad slots (j=15) ----
    for (int idx = tid; idx < NB * (NHPAD - NHID); idx += THREADS)
        spk_s[idx / (NHPAD - NHID)][NHID + idx % (NHPAD - NHID)] = 0.0f;
    if (tid < NB * NBR)
        xbuf[(tid >> 3) * 128 + 96 + (tid & 7) * 4 + 3] = 0.0f;

    // ================= neuron role: (branch kk, lane ll) =================
    const int kk = tid & 7;
    const int ll = tid >> 3;                 // 0..31
    const int NN = (ll < 8) ? 7 : 6;         // neurons: n = ll + 32m
    float alpha1[7], oma1[7], b1n[7], beta[7];
    float dst[NB][7];                        // dendrite state (this branch)
    float mem1[NB][7], spk[NB][7];           // LIF state (replicated per lane)
#pragma unroll
    for (int m = 0; m < 7; m++) {
        alpha1[m] = oma1[m] = b1n[m] = beta[m] = 0.f;
#pragma unroll
        for (int bl = 0; bl < NB; bl++) {
            dst[bl][m] = 0.f; mem1[bl][m] = 0.f; spk[bl][m] = 0.f;
        }
    }
#pragma unroll
    for (int m = 0; m < 7; m++) {
        if (m < NN) {
            const int n = ll + 32 * m;
            alpha1[m] = sigmoid_acc(tau_m1[n]);
            oma1[m]   = 1.0f - alpha1[m];
            b1n[m]    = b1[n];
            beta[m]   = sigmoid_acc(tau_n1[n * NBR + kk]);
        }
    }

    // ================= readout role: W2 chunk location =================
    const int p_ro = (tid / ODIM < NPARTS - 1) ? tid / ODIM : NPARTS - 1;
    const int o_ro = tid % ODIM;
    const int np0  = p_ro * 32;            // 32-neuron chunk (zero-pad tail)
    const float* const w2p = W2 + o_ro * NHID + np0;

    // ================= integrator params (threads 0..139) =================
    float alpha2 = 0.f, oma2 = 0.f, b2o = 0.f, mem2 = 0.f, acc = 0.f;
    if (tid < NB * ODIM) {
        alpha2 = sigmoid_acc(tau_m2[o_ro]);
        oma2   = 1.0f - alpha2;
        b2o    = b2[o_ro];
    }

    // ========= x prefetch: 240 threads x 2 consecutive floats =========
    const float* pf_ptr = nullptr;
    float* sl0 = nullptr;
    float* sl1 = nullptr;
    float2 xr = make_float2(0.f, 0.f);
    if (tid < (NB * IN_DIM) / 2) {
        const int g   = 2 * tid;
        const int blp = g / IN_DIM;
        const int i0  = g % IN_DIM;        // even
        const int c   = i0 / DFEAT;
        const int d   = i0 % DFEAT;
        int bb = b0 + blp; if (bb > B - 1) bb = B - 1;
        pf_ptr = x + ((size_t)bb * NCH + c) * T_STEPS * DFEAT + d;
        const int k0 = i0 / PER, j0 = i0 % PER;
        sl0 = &xbuf[blp * 128 + (j0 >> 2) * 32 + k0 * 4 + (j0 & 3)];
        const int i1 = i0 + 1;
        const int k1 = i1 / PER, j1 = i1 % PER;
        sl1 = &xbuf[blp * 128 + (j1 >> 2) * 32 + k1 * 4 + (j1 & 3)];
        xr = *(const float2*)pf_ptr;       // t = 0
    }

    __syncthreads();

    // ============================ time loop ============================
#pragma unroll 1
    for (int t = 0; t < T_STEPS; t++) {
        if (pf_ptr) { *sl0 = xr.x; *sl1 = xr.y; }
        __syncthreads();   // S1: xbuf ready; prior psum/spk consumers done

        if (pf_ptr) {      // prefetch t+1
            const int tn = (t + 1 < T_STEPS) ? t + 1 : t;
            xr = *(const float2*)(pf_ptr + (size_t)tn * DFEAT);
        }

        // ---- x into registers: 16 conflict-free LDS.128 ----
        float4 xq[NB][4];
#pragma unroll
        for (int bl = 0; bl < NB; bl++)
#pragma unroll
            for (int j4 = 0; j4 < 4; j4++)
                xq[bl][j4] =
                    *(const float4*)&xbuf[bl * 128 + j4 * 32 + kk * 4];

        // ---- neuron phase: stream weights, 16 MACs per 16B load ----
#pragma unroll
        for (int m = 0; m < 7; m++) {
            if (m < NN) {
                const int n = ll + 32 * m;
                const float* wp = g_wsm + n * WROW + kk * 4;
                float4 w0 = ldg128v(wp);
                float4 w1 = ldg128v(wp + 32);
                float4 w2q = ldg128v(wp + 64);
                float4 w3 = ldg128v(wp + 96);
                const ulonglong2 wu0 = *(const ulonglong2*)&w0;
                const ulonglong2 wu1 = *(const ulonglong2*)&w1;
                const ulonglong2 wu2 = *(const ulonglong2*)&w2q;
                const ulonglong2 wu3 = *(const ulonglong2*)&w3;

                float lsum[NB];
#pragma unroll
                for (int bl = 0; bl < NB; bl++) {
                    const ulonglong2 xu0 = *(const ulonglong2*)&xq[bl][0];
                    const ulonglong2 xu1 = *(const ulonglong2*)&xq[bl][1];
                    const ulonglong2 xu2 = *(const ulonglong2*)&xq[bl][2];
                    const ulonglong2 xu3 = *(const ulonglong2*)&xq[bl][3];
                    unsigned long long a0, a1;
                    a0 = ffma2(wu0.x, xu0.x, 0ull);
                    a1 = ffma2(wu0.y, xu0.y, 0ull);
                    a0 = ffma2(wu1.x, xu1.x, a0);
                    a1 = ffma2(wu1.y, xu1.y, a1);
                    a0 = ffma2(wu2.x, xu2.x, a0);
                    a1 = ffma2(wu2.y, xu2.y, a1);
                    a0 = ffma2(wu3.x, xu3.x, a0);
                    a1 = ffma2(wu3.y, xu3.y, a1);
                    float2 vv = unpack2(add2(a0, a1));
                    const float I = vv.x + vv.y;          // pads are 0*0
                    float dk = dst[bl][m];
                    dk = fmaf(beta[m], dk - I, I);        // beta*d+(1-beta)*I
                    dst[bl][m] = dk;
                    lsum[bl] = dk;
                }
                // butterfly over the 8 branch lanes -> all lanes get the sum
#pragma unroll
                for (int bl = 0; bl < NB; bl++) {
                    float v = lsum[bl];
                    v += __shfl_xor_sync(0xFFFFFFFFu, v, 1);
                    v += __shfl_xor_sync(0xFFFFFFFFu, v, 2);
                    v += __shfl_xor_sync(0xFFFFFFFFu, v, 4);
                    const float l = v + b1n[m];
                    float mv = fmaf(alpha1[m], mem1[bl][m] - spk[bl][m],
                                    oma1[m] * l);
                    mem1[bl][m] = mv;
                    const float s = (mv > 1.0f) ? 1.0f : 0.0f;
                    spk[bl][m] = s;
                    if (kk == 0) spk_s[bl][n] = s;
                }
            }
        }
        __syncthreads();   // S2: spikes visible

        // ---- readout partials: W2 chunk via predicated LDG (L1-hot) ----
        if (tid < NPARTS * ODIM) {
            float4 wq[8];
#pragma unroll
            for (int j = 0; j < 8; j++) {
                const int nb_ = np0 + 4 * j;
                wq[j] = (nb_ + 3 < NHID) ? ldg128v(w2p + 4 * j)
                                         : make_float4(0.f, 0.f, 0.f, 0.f);
            }
#pragma unroll
            for (int bl = 0; bl < NB; bl++) {
                const float4* sp = (const float4*)(&spk_s[bl][np0]);
                float s0 = 0.f, s1 = 0.f;
#pragma unroll
                for (int q = 0; q < 8; q++) {
                    float4 v = sp[q];
                    s0 = fmaf(v.x, wq[q].x, s0);
                    s1 = fmaf(v.y, wq[q].y, s1);
                    s0 = fmaf(v.z, wq[q].z, s0);
                    s1 = fmaf(v.w, wq[q].w, s1);
                }
                psum[p_ro][bl][o_ro] = s0 + s1;
            }
        }
        __syncthreads();   // S3: partials visible

        // ---- leaky readout integrator: thread (bl, o) ----
        if (tid < NB * ODIM) {
            const int bl = tid / ODIM;
            float z = b2o;
#pragma unroll
            for (int p = 0; p < NPARTS; p++) z += psum[p][bl][o_ro];
            mem2 = fmaf(alpha2, mem2, oma2 * z);
            acc += mem2;
        }
    }

    // ==================== epilogue: log_softmax(acc/T) ====================
    if (tid < NB * ODIM) accbuf[tid / ODIM][o_ro] = acc * (1.0f / (float)T_STEPS);
    __syncthreads();
    if (tid < NB * ODIM) {
        const int bl = tid / ODIM;
        const int b  = b0 + bl;
        if (b < B) {
            float m = -INFINITY;
#pragma unroll
            for (int o = 0; o < ODIM; o++) m = fmaxf(m, accbuf[bl][o]);
            float ssum = 0.0f;
#pragma unroll
            for (int o = 0; o < ODIM; o++) ssum += expf(accbuf[bl][o] - m);
            out[(size_t)b * ODIM + o_ro] = accbuf[bl][o_ro] - m - logf(ssum);
        }
    }
}

extern "C" void kernel_launch(void* const* d_in, const int* in_sizes, int n_in,
                              void* d_out, int out_size) {
    const float* x      = (const float*)d_in[0];
    const float* W1     = (const float*)d_in[1];
    const float* b1     = (const float*)d_in[2];
    const float* tau_m1 = (const float*)d_in[3];
    const float* tau_n1 = (const float*)d_in[4];
    const float* W2     = (const float*)d_in[5];
    const float* b2     = (const float*)d_in[6];
    const float* tau_m2 = (const float*)d_in[7];
    float* out = (float*)d_out;

    const int B = in_sizes[0] / (NCH * T_STEPS * DFEAT);   // 512
    const int grid = (B + NB - 1) / NB;                    // 128

    // 1) repack masked W1 into the k-interleaved device scratch (cheap,
    //    deterministic, re-run every call -> graph-capture safe)
    repack_kernel<<<(NHID * WROW) / THREADS, THREADS>>>(W1);
    // 2) main persistent kernel
    snn_kernel<<<grid, THREADS>>>(x, b1, tau_m1, tau_n1, W2, b2, tau_m2,
                                  out, B);
}

// round 14
// speedup vs baseline: 1.1166x; 1.1166x over previous
#include <cuda_runtime.h>
#include <cstdint>
#include <math.h>

// Problem constants (fixed by the reference)
#define T_STEPS 250
#define NCH     3
#define DFEAT   40
#define IN_DIM  120     // NCH*DFEAT
#define NHID    200
#define NHPAD   224     // spike row padded (zero tail) for 7x32 readout chunks
#define NBR     8
#define PER     15      // IN_DIM / NBR
#define ODIM    35
#define NB      4       // batch elements per CTA
#define NPARTS  7       // readout partial-sum parts (7*32 = 224)
#define THREADS 256
#define DPAD    9       // dsum row pad: 9 words -> conflict-free scatter+gather

// Weight scratch: chunk (m, w4, j4, lane) -> 16B, laid out so a warp's 32
// lanes at (m, j4) read 32 CONSECUTIVE chunks = contiguous 512B (coalesced).
//   chunk(m, w4, j4, lane) = ((m*8 + w4)*4 + j4)*32 + lane
//   lane = l4*8 + kk,  neuron n = 32m + 4*w4 + l4,  branch = kk
#define NCHUNK  (7 * 8 * 4 * 32)          // 7168 chunks
__device__ float g_wsm[NCHUNK * 4];       // 28672 floats = 114.7 KB

__global__ void repack_kernel(const float* __restrict__ W1) {
    const int idx = blockIdx.x * THREADS + threadIdx.x;   // < 28672
    const int e     = idx & 3;
    const int chunk = idx >> 2;
    const int lane  = chunk & 31;
    const int j4    = (chunk >> 5) & 3;
    const int w4    = (chunk >> 7) & 7;
    const int m     = chunk >> 10;        // 0..6
    const int kk    = lane & 7;
    const int l4    = lane >> 3;
    const int n     = 32 * m + 4 * w4 + l4;
    const int j     = j4 * 4 + e;
    g_wsm[idx] = (n < NHID && j < PER)
        ? W1[(size_t)(n * NBR + kk) * IN_DIM + kk * PER + j] : 0.0f;
}

// ---------------- packed f32x2 helpers (sm_100a) ----------------
__device__ __forceinline__ unsigned long long ffma2(unsigned long long a,
                                                    unsigned long long b,
                                                    unsigned long long c) {
    unsigned long long d;
    asm("fma.rn.f32x2 %0, %1, %2, %3;" : "=l"(d) : "l"(a), "l"(b), "l"(c));
    return d;
}
__device__ __forceinline__ unsigned long long add2(unsigned long long a,
                                                   unsigned long long b) {
    unsigned long long d;
    asm("add.rn.f32x2 %0, %1, %2;" : "=l"(d) : "l"(a), "l"(b));
    return d;
}
__device__ __forceinline__ float2 unpack2(unsigned long long u) {
    float lo, hi;
    asm("mov.b64 {%0, %1}, %2;" : "=f"(lo), "=f"(hi) : "l"(u));
    return make_float2(lo, hi);
}
__device__ __forceinline__ float sigmoid_acc(float v) {
    return 1.0f / (1.0f + expf(-v));
}
// Volatile LDG.128: keeps the loop-invariant weight stream OUT of persistent
// registers (hoisting it is what pegged earlier kernels at the 255-reg cap).
__device__ __forceinline__ float4 ldg128v(const float* p) {
    float4 v;
    asm volatile("ld.global.nc.v4.f32 {%0,%1,%2,%3}, [%4];"
                 : "=f"(v.x), "=f"(v.y), "=f"(v.z), "=f"(v.w) : "l"(p));
    return v;
}

// One CTA = NB=4 batch elements (grid 128 = one wave).
// Dendrite role: thread (kk = tid&7, ll = tid>>3) holds x[4 batches][branch
// kk] in 16 float4 registers (loaded once/step) and streams COALESCED weight
// chunks for neurons n = 32m + ll; each 16B weight load feeds 16 MACs.
// Branch reduction via SMEM dsum (9-padded rows, conflict-free both ways).
// LIF role: thread n (<200) sums 8 branches, updates mem/spike (regs).
__global__ void __launch_bounds__(THREADS, 1) snn_kernel(
    const float* __restrict__ x,       // [B, 3, 250, 40]
    const float* __restrict__ b1,      // [200]
    const float* __restrict__ tau_m1,  // [200]
    const float* __restrict__ tau_n1,  // [200, 8]
    const float* __restrict__ W2,      // [35, 200]
    const float* __restrict__ b2,      // [35]
    const float* __restrict__ tau_m2,  // [35]
    float* __restrict__ out,           // [B, 35]
    int B)
{
    __shared__ __align__(16) float xbuf[NB * 128];        // k-interleaved xt
    __shared__ __align__(16) float dsum[NB * NHID * DPAD];// dendrite partials
    __shared__ __align__(16) float spk_s[NB][NHPAD];      // spikes, zero tail
    __shared__ float psum[NPARTS][NB][ODIM + 1];          // readout partials
    __shared__ float accbuf[NB][ODIM];                    // log-softmax staging

    const int tid = threadIdx.x;
    const int b0  = blockIdx.x * NB;

    // ---- one-time zeroing: spike tails + xbuf pad slots (j=15) ----
    for (int idx = tid; idx < NB * (NHPAD - NHID); idx += THREADS)
        spk_s[idx / (NHPAD - NHID)][NHID + idx % (NHPAD - NHID)] = 0.0f;
    if (tid < NB * NBR)
        xbuf[(tid >> 3) * 128 + 96 + (tid & 7) * 4 + 3] = 0.0f;

    // ============ dendrite role: (branch kk, neuron-lane ll) ============
    const int kk = tid & 7;
    const int ll = tid >> 3;                 // 0..31
    const int w4 = ll >> 2;
    const int l4 = ll & 3;
    const int NN = (ll < 8) ? 7 : 6;         // m count: n = 32m + ll
    float beta[7];
    float dst[NB][7];
#pragma unroll
    for (int m = 0; m < 7; m++) {
        beta[m] = 0.f;
#pragma unroll
        for (int bl = 0; bl < NB; bl++) dst[bl][m] = 0.f;
    }
#pragma unroll
    for (int m = 0; m < 7; m++)
        if (m < NN)
            beta[m] = sigmoid_acc(tau_n1[(32 * m + ll) * NBR + kk]);

    // ============ LIF role: thread n (< 200) ============
    float alpha1 = 0.f, oma1 = 0.f, b1n = 0.f;
    float mem1[NB], spk[NB];
#pragma unroll
    for (int bl = 0; bl < NB; bl++) { mem1[bl] = 0.f; spk[bl] = 0.f; }
    if (tid < NHID) {
        alpha1 = sigmoid_acc(tau_m1[tid]);
        oma1   = 1.0f - alpha1;
        b1n    = b1[tid];
    }

    // ============ readout role: W2 chunk location ============
    const int p_ro = (tid / ODIM < NPARTS - 1) ? tid / ODIM : NPARTS - 1;
    const int o_ro = tid % ODIM;
    const int np0  = p_ro * 32;
    const float* const w2p = W2 + o_ro * NHID + np0;

    // ============ integrator role (threads 0..139) ============
    float alpha2 = 0.f, oma2 = 0.f, b2o = 0.f, mem2 = 0.f, acc = 0.f;
    if (tid < NB * ODIM) {
        alpha2 = sigmoid_acc(tau_m2[o_ro]);
        oma2   = 1.0f - alpha2;
        b2o    = b2[o_ro];
    }

    // ============ x prefetch: 240 threads x 2 consecutive floats ============
    const float* pf_ptr = nullptr;
    float* sl0 = nullptr;
    float* sl1 = nullptr;
    float2 xr = make_float2(0.f, 0.f);
    if (tid < (NB * IN_DIM) / 2) {
        const int g   = 2 * tid;
        const int blp = g / IN_DIM;
        const int i0  = g % IN_DIM;        // even
        const int c   = i0 / DFEAT;
        const int d   = i0 % DFEAT;
        int bb = b0 + blp; if (bb > B - 1) bb = B - 1;
        pf_ptr = x + ((size_t)bb * NCH + c) * T_STEPS * DFEAT + d;
        const int k0 = i0 / PER, j0 = i0 % PER;
        sl0 = &xbuf[blp * 128 + (j0 >> 2) * 32 + k0 * 4 + (j0 & 3)];
        const int i1 = i0 + 1;
        const int k1 = i1 / PER, j1 = i1 % PER;
        sl1 = &xbuf[blp * 128 + (j1 >> 2) * 32 + k1 * 4 + (j1 & 3)];
        xr = *(const float2*)pf_ptr;       // t = 0
    }

    __syncthreads();

    // ============================ time loop ============================
#pragma unroll 1
    for (int t = 0; t < T_STEPS; t++) {
        if (pf_ptr) { *sl0 = xr.x; *sl1 = xr.y; }
        __syncthreads();   // S1: xbuf ready; prior dsum/spk/psum consumers done

        if (pf_ptr) {      // prefetch t+1
            const int tn = (t + 1 < T_STEPS) ? t + 1 : t;
            xr = *(const float2*)(pf_ptr + (size_t)tn * DFEAT);
        }

        // ---- x into registers: 16 LDS.128 (8 distinct 16B per warp) ----
        float4 xq[NB][4];
#pragma unroll
        for (int bl = 0; bl < NB; bl++)
#pragma unroll
            for (int j4 = 0; j4 < 4; j4++)
                xq[bl][j4] =
                    *(const float4*)&xbuf[bl * 128 + j4 * 32 + kk * 4];

        // ---- dendrite phase: coalesced weight stream, 16 MACs / 16B ----
#pragma unroll
        for (int m = 0; m < 7; m++) {
            if (m < NN) {
                // chunk base for (m, j4=0): ((m*8+w4)*4)*32 + l4*8 + kk
                const float* wb =
                    g_wsm + (size_t)(((m * 8 + w4) * 128) + l4 * 8 + kk) * 4;
                float4 w0 = ldg128v(wb);
                float4 w1 = ldg128v(wb + 128);
                float4 w2q = ldg128v(wb + 256);
                float4 w3 = ldg128v(wb + 384);
                const ulonglong2 wu0 = *(const ulonglong2*)&w0;
                const ulonglong2 wu1 = *(const ulonglong2*)&w1;
                const ulonglong2 wu2 = *(const ulonglong2*)&w2q;
                const ulonglong2 wu3 = *(const ulonglong2*)&w3;
                const int n = 32 * m + ll;
                float* dsb = &dsum[n * DPAD + kk];
#pragma unroll
                for (int bl = 0; bl < NB; bl++) {
                    const ulonglong2 xu0 = *(const ulonglong2*)&xq[bl][0];
                    const ulonglong2 xu1 = *(const ulonglong2*)&xq[bl][1];
                    const ulonglong2 xu2 = *(const ulonglong2*)&xq[bl][2];
                    const ulonglong2 xu3 = *(const ulonglong2*)&xq[bl][3];
                    unsigned long long a0, a1;
                    a0 = ffma2(wu0.x, xu0.x, 0ull);
                    a1 = ffma2(wu0.y, xu0.y, 0ull);
                    a0 = ffma2(wu1.x, xu1.x, a0);
                    a1 = ffma2(wu1.y, xu1.y, a1);
                    a0 = ffma2(wu2.x, xu2.x, a0);
                    a1 = ffma2(wu2.y, xu2.y, a1);
                    a0 = ffma2(wu3.x, xu3.x, a0);
                    a1 = ffma2(wu3.y, xu3.y, a1);
                    float2 vv = unpack2(add2(a0, a1));
                    const float I = vv.x + vv.y;          // pads are 0*0
                    float dk = dst[bl][m];
                    dk = fmaf(beta[m], dk - I, I);        // beta*d+(1-beta)*I
                    dst[bl][m] = dk;
                    dsb[bl * (NHID * DPAD)] = dk;         // conflict-free STS
                }
            }
        }
        __syncthreads();   // S2: dendrite partials visible

        // ---- LIF phase: thread n sums 8 branches, updates mem/spike ----
        if (tid < NHID) {
#pragma unroll
            for (int bl = 0; bl < NB; bl++) {
                const float* dr = &dsum[bl * (NHID * DPAD) + tid * DPAD];
                float l = b1n;
#pragma unroll
                for (int k = 0; k < NBR; k++) l += dr[k];
                float mv = fmaf(alpha1, mem1[bl] - spk[bl], oma1 * l);
                mem1[bl] = mv;
                const float s = (mv > 1.0f) ? 1.0f : 0.0f;
                spk[bl] = s;
                spk_s[bl][tid] = s;
            }
        }
        __syncthreads();   // S3: spikes visible

        // ---- readout partials: W2 chunk via predicated LDG (L1-hot) ----
        if (tid < NPARTS * ODIM) {
            float4 wq[8];
#pragma unroll
            for (int j = 0; j < 8; j++) {
                const int nb_ = np0 + 4 * j;
                wq[j] = (nb_ + 3 < NHID) ? ldg128v(w2p + 4 * j)
                                         : make_float4(0.f, 0.f, 0.f, 0.f);
            }
#pragma unroll
            for (int bl = 0; bl < NB; bl++) {
                const float4* sp = (const float4*)(&spk_s[bl][np0]);
                float s0 = 0.f, s1 = 0.f;
#pragma unroll
                for (int q = 0; q < 8; q++) {
                    float4 v = sp[q];
                    s0 = fmaf(v.x, wq[q].x, s0);
                    s1 = fmaf(v.y, wq[q].y, s1);
                    s0 = fmaf(v.z, wq[q].z, s0);
                    s1 = fmaf(v.w, wq[q].w, s1);
                }
                psum[p_ro][bl][o_ro] = s0 + s1;
            }
        }
        __syncthreads();   // S4: partials visible

        // ---- leaky readout integrator: thread (bl, o) ----
        if (tid < NB * ODIM) {
            const int bl = tid / ODIM;
            float z = b2o;
#pragma unroll
            for (int p = 0; p < NPARTS; p++) z += psum[p][bl][o_ro];
            mem2 = fmaf(alpha2, mem2, oma2 * z);
            acc += mem2;
        }
    }

    // ==================== epilogue: log_softmax(acc/T) ====================
    if (tid < NB * ODIM) accbuf[tid / ODIM][o_ro] = acc * (1.0f / (float)T_STEPS);
    __syncthreads();
    if (tid < NB * ODIM) {
        const int bl = tid / ODIM;
        const int b  = b0 + bl;
        if (b < B) {
            float m = -INFINITY;
#pragma unroll
            for (int o = 0; o < ODIM; o++) m = fmaxf(m, accbuf[bl][o]);
            float ssum = 0.0f;
#pragma unroll
            for (int o = 0; o < ODIM; o++) ssum += expf(accbuf[bl][o] - m);
            out[(size_t)b * ODIM + o_ro] = accbuf[bl][o_ro] - m - logf(ssum);
        }
    }
}

extern "C" void kernel_launch(void* const* d_in, const int* in_sizes, int n_in,
                              void* d_out, int out_size) {
    const float* x      = (const float*)d_in[0];
    const float* W1     = (const float*)d_in[1];
    const float* b1     = (const float*)d_in[2];
    const float* tau_m1 = (const float*)d_in[3];
    const float* tau_n1 = (const float*)d_in[4];
    const float* W2     = (const float*)d_in[5];
    const float* b2     = (const float*)d_in[6];
    const float* tau_m2 = (const float*)d_in[7];
    float* out = (float*)d_out;

    const int B = in_sizes[0] / (NCH * T_STEPS * DFEAT);   // 512
    const int grid = (B + NB - 1) / NB;                    // 128

    // 1) repack masked W1 into the warp-coalesced device scratch
    repack_kernel<<<(NCHUNK * 4) / THREADS, THREADS>>>(W1);
    // 2) main persistent kernel
    snn_kernel<<<grid, THREADS>>>(x, b1, tau_m1, tau_n1, W2, b2, tau_m2,
                                  out, B);
}

// round 15
// speedup vs baseline: 1.3880x; 1.2431x over previous
#include <cuda_runtime.h>
#include <cstdint>
#include <math.h>

// Problem constants (fixed by the reference)
#define T_STEPS 250
#define NCH     3
#define DFEAT   40
#define IN_DIM  120     // NCH*DFEAT
#define NHID    200
#define NBR     8
#define PER     15      // IN_DIM / NBR
#define PERP    16      // padded per-branch stride in xbuf (16B-aligned pairs)
#define XPAD    (NBR*PERP)   // 128
#define ODIM    35
#define NB      4       // batch elements per CTA
#define THREADS 256
#define RBASE   116     // readout slots live on tid 116..255 (140 slots)
#define W2S     212     // w2s row stride: 8 rows/warp spread over all banks

// ---------------- packed f32x2 helpers (sm_100a) ----------------
__device__ __forceinline__ unsigned long long ffma2(unsigned long long a,
                                                    unsigned long long b,
                                                    unsigned long long c) {
    unsigned long long d;
    asm("fma.rn.f32x2 %0, %1, %2, %3;" : "=l"(d) : "l"(a), "l"(b), "l"(c));
    return d;
}
__device__ __forceinline__ unsigned long long add2(unsigned long long a,
                                                   unsigned long long b) {
    unsigned long long d;
    asm("add.rn.f32x2 %0, %1, %2;" : "=l"(d) : "l"(a), "l"(b));
    return d;
}
__device__ __forceinline__ unsigned long long pack2(float lo, float hi) {
    unsigned long long u;
    asm("mov.b64 %0, {%1, %2};" : "=l"(u) : "f"(lo), "f"(hi));
    return u;
}
__device__ __forceinline__ float2 unpack2(unsigned long long u) {
    float lo, hi;
    asm("mov.b64 {%0, %1}, %2;" : "=f"(lo), "=f"(hi) : "l"(u));
    return make_float2(lo, hi);
}
__device__ __forceinline__ float sigmoid_acc(float v) {
    return 1.0f / (1.0f + expf(-v));
}
// Volatile shared LDS.128: stops ptxas hoisting the loop-invariant W2 row
// (50 x 16B) into 200 persistent registers across the time loop.
__device__ __forceinline__ float4 lds128v(uint32_t addr) {
    float4 v;
    asm volatile("ld.shared.v4.f32 {%0,%1,%2,%3}, [%4];"
                 : "=f"(v.x), "=f"(v.y), "=f"(v.z), "=f"(v.w) : "r"(addr));
    return v;
}

// One CTA = NB=4 batch elements (grid 128 = one wave). Thread n (<200) owns
// neuron n for 4 batches (R4/R12 proven core). NEW: readout+integrator for
// step t-1 runs IN THE SAME PHASE as neuron step t on double-buffered spikes
// (threads 116..255, one (batch,out) slot each, full 200-dot, state in regs).
// -> ONE barrier per step instead of three; psum and integrator phases gone.
__global__ void __launch_bounds__(THREADS, 1) snn_kernel(
    const float* __restrict__ x,       // [B, 3, 250, 40]
    const float* __restrict__ W1,      // [200, 8, 120]
    const float* __restrict__ b1,      // [200]
    const float* __restrict__ tau_m1,  // [200]
    const float* __restrict__ tau_n1,  // [200, 8]
    const float* __restrict__ W2,      // [35, 200]
    const float* __restrict__ b2,      // [35]
    const float* __restrict__ tau_m2,  // [35]
    float* __restrict__ out,           // [B, 35]
    int B)
{
    __shared__ __align__(16) float xbuf[2][NB][XPAD];     // double-buffered xt
    __shared__ __align__(16) float spk_s[2][NB][NHID];    // double-buffered spk
    __shared__ __align__(16) float w2s[ODIM][W2S];        // W2 rows, bank-spread
    __shared__ float accbuf[NB][ODIM];                    // integrator results

    const int tid = threadIdx.x;
    const int b0  = blockIdx.x * NB;

    // ---- one-time: W2 rows into SMEM + zero xbuf pad slots (j=15) ----
    for (int idx = tid; idx < ODIM * NHID; idx += THREADS)
        w2s[idx / NHID][idx % NHID] = W2[idx];
    if (tid < 2 * NB * NBR) {
        const int p = tid / (NB * NBR);
        const int r = tid % (NB * NBR);
        xbuf[p][r >> 3][(r & 7) * PERP + PER] = 0.0f;
    }

    // ================= neuron role: thread n (< 200) =================
    unsigned long long wp[NBR * 7];   // 7 packed weight pairs per branch
    float w14[NBR];                   // 15th (scalar) weight per branch
    float beta[NBR];
    float dst[NB][NBR];
    float mem1[NB], spk[NB];
    float alpha1 = 0.f, oma1 = 0.f, b1n = 0.f;
#pragma unroll
    for (int bl = 0; bl < NB; bl++) {
        mem1[bl] = 0.f; spk[bl] = 0.f;
#pragma unroll
        for (int k = 0; k < NBR; k++) dst[bl][k] = 0.f;
    }
    if (tid < NHID) {
        const int n = tid;
        alpha1 = sigmoid_acc(tau_m1[n]);
        oma1   = 1.0f - alpha1;
        b1n    = b1[n];
#pragma unroll
        for (int k = 0; k < NBR; k++) {
            beta[k] = sigmoid_acc(tau_n1[n * NBR + k]);
            const float* wrow = W1 + (size_t)(n * NBR + k) * IN_DIM + k * PER;
#pragma unroll
            for (int j = 0; j < 7; j++)
                wp[k * 7 + j] = pack2(wrow[2 * j], wrow[2 * j + 1]);
            w14[k] = wrow[14];
        }
    } else {
#pragma unroll
        for (int m = 0; m < NBR * 7; m++) wp[m] = 0ull;
#pragma unroll
        for (int k = 0; k < NBR; k++) { beta[k] = 0.f; w14[k] = 0.f; }
    }

    // ========= readout role: tid >= RBASE, slot = (batch blr, output orr) ====
    const int slot = (tid >= RBASE) ? tid - RBASE : 0;    // 0..139
    const int blr  = slot & 3;
    const int orr  = slot >> 2;                           // 0..34
    const uint32_t w2a =
        (uint32_t)__cvta_generic_to_shared(&w2s[orr][0]);
    float alpha2 = 0.f, oma2 = 0.f, b2o = 0.f, mem2 = 0.f, acc = 0.f;
    if (tid >= RBASE) {
        alpha2 = sigmoid_acc(tau_m2[orr]);
        oma2   = 1.0f - alpha2;
        b2o    = b2[orr];
    }

    // ========= x ingest role: 240 threads x 2 consecutive floats =========
    const float* pf_ptr = nullptr;
    int of0 = 0, of1 = 0;
    float2 xr = make_float2(0.f, 0.f);
    if (tid < (NB * IN_DIM) / 2) {
        const int g   = 2 * tid;
        const int blp = g / IN_DIM;
        const int i0  = g % IN_DIM;        // even
        const int c   = i0 / DFEAT;
        const int d   = i0 % DFEAT;
        int bb = b0 + blp; if (bb > B - 1) bb = B - 1;
        pf_ptr = x + ((size_t)bb * NCH + c) * T_STEPS * DFEAT + d;
        of0 = blp * XPAD + (i0 / PER) * PERP + (i0 % PER);
        const int i1 = i0 + 1;
        of1 = blp * XPAD + (i1 / PER) * PERP + (i1 % PER);
        xr = *(const float2*)pf_ptr;       // t = 0
    }

    float* const xb_flat = &xbuf[0][0][0];

    __syncthreads();

    // ============================ time loop ============================
#pragma unroll 1
    for (int t = 0; t < T_STEPS; t++) {
        const int p = t & 1;
        // scatter xt into buffer p
        if (pf_ptr) {
            float* xb = xb_flat + p * (NB * XPAD);
            xb[of0] = xr.x; xb[of1] = xr.y;
        }
        __syncthreads();   // THE one barrier: x(t) ready; spikes(t-1) ready;
                           // readout(t-2) done with buffer p

        if (pf_ptr) {      // prefetch t+1
            const int tn = (t + 1 < T_STEPS) ? t + 1 : t;
            xr = *(const float2*)(pf_ptr + (size_t)tn * DFEAT);
        }

        // ---- neuron step t (reads xbuf[p], writes spk_s[p]) ----
        if (tid < NHID) {
#pragma unroll
            for (int bl = 0; bl < NB; bl++) {
                float l = b1n;
#pragma unroll
                for (int k = 0; k < NBR; k++) {
                    const ulonglong2* xp =
                        (const ulonglong2*)(&xbuf[p][bl][k * PERP]);
                    ulonglong2 q0 = xp[0];
                    ulonglong2 q1 = xp[1];
                    unsigned long long a0, a1;
                    a0 = ffma2(wp[k * 7 + 0], q0.x, 0ull);
                    a1 = ffma2(wp[k * 7 + 1], q0.y, 0ull);
                    a0 = ffma2(wp[k * 7 + 2], q1.x, a0);
                    a1 = ffma2(wp[k * 7 + 3], q1.y, a1);
                    ulonglong2 q2 = xp[2];
                    a0 = ffma2(wp[k * 7 + 4], q2.x, a0);
                    a1 = ffma2(wp[k * 7 + 5], q2.y, a1);
                    ulonglong2 q3 = xp[3];
                    a0 = ffma2(wp[k * 7 + 6], q3.x, a0);
                    float2 vv  = unpack2(add2(a0, a1));
                    float2 hx  = unpack2(q3.y);          // (x14, pad)
                    float  I   = fmaf(w14[k], hx.x, vv.x + vv.y);
                    float  dk  = dst[bl][k];
                    dk = fmaf(beta[k], dk - I, I);       // beta*d + (1-beta)*I
                    dst[bl][k] = dk;
                    l += dk;
                }
                float m = fmaf(alpha1, mem1[bl] - spk[bl], oma1 * l);
                mem1[bl] = m;
                float s = (m > 1.0f) ? 1.0f : 0.0f;
                spk[bl] = s;
                spk_s[p][bl][tid] = s;
            }
        }

        // ---- readout + integrator for step t-1 (buffer p^1), in-phase ----
        if (t > 0 && tid >= RBASE) {
            const ulonglong2* sp =
                (const ulonglong2*)&spk_s[p ^ 1][blr][0];
            unsigned long long a0 = 0ull, a1 = 0ull;
#pragma unroll 10
            for (int j = 0; j < NHID / 4; j++) {   // 50 x 4 neurons
                float4 wv = lds128v(w2a + 16u * j);
                const ulonglong2 wq = *(const ulonglong2*)&wv;
                const ulonglong2 sq = sp[j];
                a0 = ffma2(wq.x, sq.x, a0);
                a1 = ffma2(wq.y, sq.y, a1);
            }
            float2 dv = unpack2(add2(a0, a1));
            const float z = dv.x + dv.y + b2o;
            mem2 = fmaf(alpha2, mem2, oma2 * z);
            acc += mem2;
        }
        // next iteration's barrier orders everything
    }

    // ---- tail: readout for step T-1 (parity (T-1)&1) ----
    __syncthreads();
    if (tid >= RBASE) {
        const ulonglong2* sp =
            (const ulonglong2*)&spk_s[(T_STEPS - 1) & 1][blr][0];
        unsigned long long a0 = 0ull, a1 = 0ull;
#pragma unroll 10
        for (int j = 0; j < NHID / 4; j++) {
            float4 wv = lds128v(w2a + 16u * j);
            const ulonglong2 wq = *(const ulonglong2*)&wv;
            const ulonglong2 sq = sp[j];
            a0 = ffma2(wq.x, sq.x, a0);
            a1 = ffma2(wq.y, sq.y, a1);
        }
        float2 dv = unpack2(add2(a0, a1));
        const float z = dv.x + dv.y + b2o;
        mem2 = fmaf(alpha2, mem2, oma2 * z);
        acc += mem2;
        accbuf[blr][orr] = acc * (1.0f / (float)T_STEPS);
    }
    __syncthreads();

    // ==================== epilogue: log_softmax ====================
    if (tid < NB * ODIM) {
        const int bl = tid / ODIM;
        const int o  = tid % ODIM;
        const int b  = b0 + bl;
        if (b < B) {
            float m = -INFINITY;
#pragma unroll
            for (int j = 0; j < ODIM; j++) m = fmaxf(m, accbuf[bl][j]);
            float ssum = 0.0f;
#pragma unroll
            for (int j = 0; j < ODIM; j++) ssum += expf(accbuf[bl][j] - m);
            out[(size_t)b * ODIM + o] = accbuf[bl][o] - m - logf(ssum);
        }
    }
}

extern "C" void kernel_launch(void* const* d_in, const int* in_sizes, int n_in,
                              void* d_out, int out_size) {
    const float* x      = (const float*)d_in[0];
    const float* W1     = (const float*)d_in[1];
    const float* b1     = (const float*)d_in[2];
    const float* tau_m1 = (const float*)d_in[3];
    const float* tau_n1 = (const float*)d_in[4];
    const float* W2     = (const float*)d_in[5];
    const float* b2     = (const float*)d_in[6];
    const float* tau_m2 = (const float*)d_in[7];
    float* out = (float*)d_out;

    const int B = in_sizes[0] / (NCH * T_STEPS * DFEAT);   // 512
    const int grid = (B + NB - 1) / NB;                    // 128
    snn_kernel<<<grid, THREADS>>>(x, W1, b1, tau_m1, tau_n1, W2, b2, tau_m2,
                                  out, B);
}

// round 17
// speedup vs baseline: 1.4785x; 1.0652x over previous
#include <cuda_runtime.h>
#include <cstdint>
#include <math.h>

// Problem constants (fixed by the reference)
#define T_STEPS 250
#define NCH     3
#define DFEAT   40
#define IN_DIM  120     // NCH*DFEAT
#define NHID    200
#define NHPAD   224     // spike row padded (zero tail) for 7x32 readout chunks
#define NBR     8
#define PER     15      // IN_DIM / NBR
#define PERP    16      // padded per-branch stride in xbuf (16B-aligned pairs)
#define XPAD    (NBR*PERP)   // 128
#define ODIM    35
#define NB      4       // batch elements per CTA
#define NPARTS  7       // readout partial-sum parts (7*32 = 224)
#define TB      2       // time-block: steps per barrier phase
#define NPHASE  (T_STEPS/TB)   // 125
#define THREADS 256

// ---------------- packed f32x2 helpers (sm_100a) ----------------
__device__ __forceinline__ unsigned long long ffma2(unsigned long long a,
                                                    unsigned long long b,
                                                    unsigned long long c) {
    unsigned long long d;
    asm("fma.rn.f32x2 %0, %1, %2, %3;" : "=l"(d) : "l"(a), "l"(b), "l"(c));
    return d;
}
__device__ __forceinline__ unsigned long long add2(unsigned long long a,
                                                   unsigned long long b) {
    unsigned long long d;
    asm("add.rn.f32x2 %0, %1, %2;" : "=l"(d) : "l"(a), "l"(b));
    return d;
}
__device__ __forceinline__ unsigned long long pack2(float lo, float hi) {
    unsigned long long u;
    asm("mov.b64 %0, {%1, %2};" : "=l"(u) : "f"(lo), "f"(hi));
    return u;
}
__device__ __forceinline__ float2 unpack2(unsigned long long u) {
    float lo, hi;
    asm("mov.b64 {%0, %1}, %2;" : "=f"(lo), "=f"(hi) : "l"(u));
    return make_float2(lo, hi);
}
__device__ __forceinline__ float sigmoid_acc(float v) {
    return 1.0f / (1.0f + expf(-v));
}
// Volatile LDG.128 (L1-cached, read-only): stops the compiler hoisting the
// loop-invariant W2 chunk into 32 persistent registers.
__device__ __forceinline__ float4 ldg128v(const float* p) {
    float4 v;
    asm volatile("ld.global.nc.v4.f32 {%0,%1,%2,%3}, [%4];"
                 : "=f"(v.x), "=f"(v.y), "=f"(v.z), "=f"(v.w) : "l"(p));
    return v;
}

// One CTA handles NB=4 batch elements (grid 128 = one wave). Thread n (<200)
// owns neuron n for all 4 batches; dendritic weights live in registers.
// TB=2 time-blocking (R12 core). R16 change: the integrator phase is
// pipelined one phase behind and runs right after S1 (reading the previous
// phase's psum) -> TWO barriers per 2-step phase instead of three, and the
// integrator overlaps the neuron phase instead of costing its own drain.
__global__ void __launch_bounds__(THREADS, 1) snn_kernel(
    const float* __restrict__ x,       // [B, 3, 250, 40]
    const float* __restrict__ W1,      // [200, 8, 120]
    const float* __restrict__ b1,      // [200]
    const float* __restrict__ tau_m1,  // [200]
    const float* __restrict__ tau_n1,  // [200, 8]
    const float* __restrict__ W2,      // [35, 200]
    const float* __restrict__ b2,      // [35]
    const float* __restrict__ tau_m2,  // [35]
    float* __restrict__ out,           // [B, 35]
    int B)
{
    __shared__ __align__(16) float xbuf[TB][NB][XPAD];    // per-step xt
    __shared__ __align__(16) float spk_s[TB][NB][NHPAD];  // spikes, zero tail
    __shared__ float psum[TB][NPARTS][NB][ODIM + 1];      // readout partials
    __shared__ float accbuf[NB][ODIM];                    // log-softmax staging

    const int tid = threadIdx.x;
    const int b0  = blockIdx.x * NB;

    // ---- one-time: zero spike tails + xbuf pad slots ----
    for (int idx = tid; idx < TB * NB * (NHPAD - NHID); idx += THREADS) {
        const int s  = idx / (NB * (NHPAD - NHID));
        const int r  = idx % (NB * (NHPAD - NHID));
        spk_s[s][r / (NHPAD - NHID)][NHID + r % (NHPAD - NHID)] = 0.0f;
    }
    if (tid < TB * NB * NBR) {
        const int s = tid / (NB * NBR);
        const int r = tid % (NB * NBR);
        xbuf[s][r >> 3][(r & 7) * PERP + PER] = 0.0f;     // pad j=15
    }

    // ================= per-neuron params + packed weights =================
    unsigned long long wp[NBR * 7];   // 7 packed pairs per branch
    float w14[NBR];                   // 15th (scalar) weight per branch
    float beta[NBR];
    float dst[NB][NBR];
    float mem1[NB], spk[NB];
    float alpha1 = 0.f, oma1 = 0.f, b1n = 0.f;
#pragma unroll
    for (int bl = 0; bl < NB; bl++) {
        mem1[bl] = 0.f; spk[bl] = 0.f;
#pragma unroll
        for (int k = 0; k < NBR; k++) dst[bl][k] = 0.f;
    }
    if (tid < NHID) {
        const int n = tid;
        alpha1 = sigmoid_acc(tau_m1[n]);
        oma1   = 1.0f - alpha1;
        b1n    = b1[n];
#pragma unroll
        for (int k = 0; k < NBR; k++) {
            beta[k] = sigmoid_acc(tau_n1[n * NBR + k]);
            const float* wrow = W1 + (size_t)(n * NBR + k) * IN_DIM + k * PER;
#pragma unroll
            for (int j = 0; j < 7; j++)
                wp[k * 7 + j] = pack2(wrow[2 * j], wrow[2 * j + 1]);
            w14[k] = wrow[14];
        }
    } else {
#pragma unroll
        for (int m = 0; m < NBR * 7; m++) wp[m] = 0ull;
#pragma unroll
        for (int k = 0; k < NBR; k++) { beta[k] = 0.f; w14[k] = 0.f; }
    }

    // ================= readout role: W2 chunk location =================
    const int p_ro = (tid / ODIM < NPARTS - 1) ? tid / ODIM : NPARTS - 1;
    const int o_ro = tid % ODIM;
    const int np0  = p_ro * 32;            // 32-neuron chunk (zero-pad tail)
    const float* const w2p = W2 + o_ro * NHID + np0;

    // ================= integrator params (threads 0..139) =================
    float alpha2 = 0.f, oma2 = 0.f, b2o = 0.f, mem2 = 0.f, acc = 0.f;
    if (tid < NB * ODIM) {
        alpha2 = sigmoid_acc(tau_m2[o_ro]);   // o_ro == tid % ODIM
        oma2   = 1.0f - alpha2;
        b2o    = b2[o_ro];
    }

    // ========= x prefetch: 240 threads x 2 floats x TB steps =========
    const float* pf_ptr = nullptr;
    int of0 = 0, of1 = 0;                 // element offsets within one buffer
    float2 xr0 = make_float2(0.f, 0.f);   // step 2t
    float2 xr1 = make_float2(0.f, 0.f);   // step 2t+1
    if (tid < (NB * IN_DIM) / 2) {
        const int g   = 2 * tid;
        const int blp = g / IN_DIM;
        const int i0  = g % IN_DIM;
        const int c   = i0 / DFEAT;
        const int d   = i0 % DFEAT;
        int bb = b0 + blp; if (bb > B - 1) bb = B - 1;
        pf_ptr = x + ((size_t)bb * NCH + c) * T_STEPS * DFEAT + d;
        of0 = blp * XPAD + (i0 / PER) * PERP + (i0 % PER);
        const int i1 = i0 + 1;
        of1 = blp * XPAD + (i1 / PER) * PERP + (i1 % PER);
        xr0 = *(const float2*)pf_ptr;                       // t = 0
        xr1 = *(const float2*)(pf_ptr + DFEAT);             // t = 1
    }

    float* const xb0 = &xbuf[0][0][0];
    float* const xb1 = &xbuf[1][0][0];

    __syncthreads();   // zeros + prefetch ready

    // ============================ phase loop ============================
#pragma unroll 1
    for (int t = 0; t < NPHASE; t++) {
        // scatter both steps' xt (registers -> padded smem)
        if (pf_ptr) {
            xb0[of0] = xr0.x; xb0[of1] = xr0.y;
            xb1[of0] = xr1.x; xb1[of1] = xr1.y;
        }
        __syncthreads();   // S1: xbuf ready; prev-phase psum complete;
                           // prior spk consumers done

        // prefetch next phase (hidden under this phase's compute)
        if (pf_ptr) {
            int tn0 = 2 * t + 2; if (tn0 > T_STEPS - 1) tn0 = T_STEPS - 1;
            int tn1 = 2 * t + 3; if (tn1 > T_STEPS - 1) tn1 = T_STEPS - 1;
            xr0 = *(const float2*)(pf_ptr + (size_t)tn0 * DFEAT);
            xr1 = *(const float2*)(pf_ptr + (size_t)tn1 * DFEAT);
        }

        // ---- integrator for PREVIOUS phase's psum (pipelined, no barrier;
        //      psum[s] is stable from prev S2 until this phase's S2) ----
        if (t > 0 && tid < NB * ODIM) {
            const int bl = tid / ODIM;
#pragma unroll
            for (int s = 0; s < TB; s++) {
                float z = b2o;
#pragma unroll
                for (int p = 0; p < NPARTS; p++) z += psum[s][p][bl][o_ro];
                mem2 = fmaf(alpha2, mem2, oma2 * z);
                acc += mem2;
            }
        }

        // ---- neuron phase: advance TB=2 steps, all 4 batches ----
        if (tid < NHID) {
#pragma unroll
            for (int s = 0; s < TB; s++) {
#pragma unroll
                for (int bl = 0; bl < NB; bl++) {
                    float l = b1n;
#pragma unroll
                    for (int k = 0; k < NBR; k++) {
                        const ulonglong2* xp =
                            (const ulonglong2*)(&xbuf[s][bl][k * PERP]);
                        ulonglong2 q0 = xp[0];
                        ulonglong2 q1 = xp[1];
                        unsigned long long a0, a1;
                        a0 = ffma2(wp[k * 7 + 0], q0.x, 0ull);
                        a1 = ffma2(wp[k * 7 + 1], q0.y, 0ull);
                        a0 = ffma2(wp[k * 7 + 2], q1.x, a0);
                        a1 = ffma2(wp[k * 7 + 3], q1.y, a1);
                        ulonglong2 q2 = xp[2];
                        a0 = ffma2(wp[k * 7 + 4], q2.x, a0);
                        a1 = ffma2(wp[k * 7 + 5], q2.y, a1);
                        ulonglong2 q3 = xp[3];
                        a0 = ffma2(wp[k * 7 + 6], q3.x, a0);
                        float2 vv  = unpack2(add2(a0, a1));
                        float2 hx  = unpack2(q3.y);        // (x14, pad)
                        float  I   = fmaf(w14[k], hx.x, vv.x + vv.y);
                        float  dk  = dst[bl][k];
                        dk = fmaf(beta[k], dk - I, I);     // beta*d+(1-beta)*I
                        dst[bl][k] = dk;
                        l += dk;
                    }
                    // soft-reset LIF
                    float m = fmaf(alpha1, mem1[bl] - spk[bl], oma1 * l);
                    mem1[bl] = m;
                    float sv = (m > 1.0f) ? 1.0f : 0.0f;
                    spk[bl] = sv;
                    spk_s[s][bl][tid] = sv;
                }
            }
        }
        __syncthreads();   // S2: both steps' spikes visible; prev psum
                           // fully consumed (integrator ran before this)

        // ---- readout partials: W2 chunk via predicated LDG (L1-hot) ----
        if (tid < NPARTS * ODIM) {
            float4 wq[8];
#pragma unroll
            for (int j = 0; j < 8; j++) {
                const int nb_ = np0 + 4 * j;
                wq[j] = (nb_ + 3 < NHID) ? ldg128v(w2p + 4 * j)
                                         : make_float4(0.f, 0.f, 0.f, 0.f);
            }
#pragma unroll
            for (int s = 0; s < TB; s++) {
#pragma unroll
                for (int bl = 0; bl < NB; bl++) {
                    const float4* sp = (const float4*)(&spk_s[s][bl][np0]);
                    float s0 = 0.f, s1 = 0.f;
#pragma unroll
                    for (int q = 0; q < 8; q++) {
                        float4 v = sp[q];
                        s0 = fmaf(v.x, wq[q].x, s0);
                        s1 = fmaf(v.y, wq[q].y, s1);
                        s0 = fmaf(v.z, wq[q].z, s0);
                        s1 = fmaf(v.w, wq[q].w, s1);
                    }
                    psum[s][p_ro][bl][o_ro] = s0 + s1;
                }
            }
        }
        // NO barrier here: next iteration's S1 publishes psum to the
        // integrator, which runs before this phase's psum is overwritten.
    }

    // ---- tail: integrate the final phase's psum ----
    __syncthreads();
    if (tid < NB * ODIM) {
        const int bl = tid / ODIM;
#pragma unroll
        for (int s = 0; s < TB; s++) {
            float z = b2o;
#pragma unroll
            for (int p = 0; p < NPARTS; p++) z += psum[s][p][bl][o_ro];
            mem2 = fmaf(alpha2, mem2, oma2 * z);
            acc += mem2;
        }
        accbuf[bl][o_ro] = acc * (1.0f / (float)T_STEPS);
    }
    __syncthreads();

    // ==================== epilogue: log_softmax(acc/T) ====================
    if (tid < NB * ODIM) {
        const int bl = tid / ODIM;
        const int b  = b0 + bl;
        if (b < B) {
            float m = -INFINITY;
#pragma unroll
            for (int o = 0; o < ODIM; o++) m = fmaxf(m, accbuf[bl][o]);
            float ssum = 0.0f;
#pragma unroll
            for (int o = 0; o < ODIM; o++) ssum += expf(accbuf[bl][o] - m);
            out[(size_t)b * ODIM + o_ro] = accbuf[bl][o_ro] - m - logf(ssum);
        }
    }
}

extern "C" void kernel_launch(void* const* d_in, const int* in_sizes, int n_in,
                              void* d_out, int out_size) {
    const float* x      = (const float*)d_in[0];
    const float* W1     = (const float*)d_in[1];
    const float* b1     = (const float*)d_in[2];
    const float* tau_m1 = (const float*)d_in[3];
    const float* tau_n1 = (const float*)d_in[4];
    const float* W2     = (const float*)d_in[5];
    const float* b2     = (const float*)d_in[6];
    const float* tau_m2 = (const float*)d_in[7];
    float* out = (float*)d_out;

    const int B = in_sizes[0] / (NCH * T_STEPS * DFEAT);   // 512
    const int grid = (B + NB - 1) / NB;                    // 128
    snn_kernel<<<grid, THREADS>>>(x, W1, b1, tau_m1, tau_n1, W2, b2, tau_m2,
                                  out, B);
}